// round 7
// baseline (speedup 1.0000x reference)
#include <cuda_runtime.h>
#include <cuda_bf16.h>
#include <math.h>
#include <stdint.h>

#define N_TOK 65536
#define HDIM  1024
#define NEXP  3
#define NCH   48          // 3*1024/64 : K-concat chunks (hi*hi, lo*hi, hi*lo)
#define BM    128
#define BN    128

typedef __nv_bfloat16 bf16;

// ------------------- scratch (allocation-free) -------------------
__device__ int  g_cursor[NEXP];
__device__ int  g_idx[NEXP * N_TOK];
__device__ bf16 g_xhi[(size_t)N_TOK * HDIM];
__device__ bf16 g_xlo[(size_t)N_TOK * HDIM];
__device__ bf16 g_ihi[(size_t)N_TOK * HDIM];
__device__ bf16 g_ilo[(size_t)N_TOK * HDIM];
__device__ bf16 g_w1hi[(size_t)NEXP * HDIM * HDIM];
__device__ bf16 g_w1lo[(size_t)NEXP * HDIM * HDIM];
__device__ bf16 g_w3hi[(size_t)NEXP * HDIM * HDIM];
__device__ bf16 g_w3lo[(size_t)NEXP * HDIM * HDIM];
__device__ bf16 g_w2hi[(size_t)NEXP * HDIM * HDIM];
__device__ bf16 g_w2lo[(size_t)NEXP * HDIM * HDIM];

// ------------------- helpers -------------------
__device__ __forceinline__ uint32_t s2u(const void* p) {
    return (uint32_t)__cvta_generic_to_shared(p);
}
__device__ __forceinline__ void cp16(uint32_t dst, const void* src) {
    asm volatile("cp.async.cg.shared.global [%0], [%1], 16;" :: "r"(dst), "l"(src));
}
#define CP_COMMIT() asm volatile("cp.async.commit_group;" ::: "memory")
#define CP_WAIT(n)  asm volatile("cp.async.wait_group %0;" :: "n"(n) : "memory")

#define LDSM4(r0,r1,r2,r3,addr) \
    asm volatile("ldmatrix.sync.aligned.m8n8.x4.shared.b16 {%0,%1,%2,%3}, [%4];" \
        : "=r"(r0), "=r"(r1), "=r"(r2), "=r"(r3) : "r"(addr))

#define MMA16816(d, a0,a1,a2,a3, b0,b1) \
    asm volatile("mma.sync.aligned.m16n8k16.row.col.f32.bf16.bf16.f32 " \
        "{%0,%1,%2,%3}, {%4,%5,%6,%7}, {%8,%9}, {%0,%1,%2,%3};" \
        : "+f"((d)[0]), "+f"((d)[1]), "+f"((d)[2]), "+f"((d)[3]) \
        : "r"(a0), "r"(a1), "r"(a2), "r"(a3), "r"(b0), "r"(b1))

__device__ __forceinline__ uint32_t swz(uint32_t o) { return o ^ ((o >> 3) & 0x70); }

__device__ __forceinline__ float act_fn(float h1, int e) {
    if (e == 0) return h1 / (1.0f + __expf(-h1));
    if (e == 1) return 0.5f * h1 * (1.0f + erff(h1 * 0.70710678118654752f));
    return fmaxf(h1, 0.0f);
}
__device__ __forceinline__ uint32_t pack_bf2(float a, float b) {
    __nv_bfloat162 t = __halves2bfloat162(__float2bfloat16_rn(a), __float2bfloat16_rn(b));
    return *(uint32_t*)&t;
}

// ============================================================
// Kernel 0: zero per-expert cursors
// ============================================================
__global__ void zero_kernel() {
    if (threadIdx.x < NEXP) g_cursor[threadIdx.x] = 0;
}

// ============================================================
// Kernel 1: gating (one warp per token)
// ============================================================
__global__ void gate_kernel(const float* __restrict__ x,
                            const float* __restrict__ Wg,
                            const float* __restrict__ bg,
                            const float* __restrict__ gu) {
    __shared__ float sWg[HDIM * NEXP];
    int tid = threadIdx.x;
    for (int t = tid; t < HDIM * NEXP; t += blockDim.x) sWg[t] = Wg[t];
    __syncthreads();

    int warp = tid >> 5, lane = tid & 31;
    int n = blockIdx.x * 8 + warp;
    const float* xr = x + (size_t)n * HDIM;

    float a0 = 0.f, a1 = 0.f, a2 = 0.f;
    #pragma unroll 8
    for (int j = 0; j < HDIM; j += 32) {
        float xi = xr[j + lane];
        const float* w = &sWg[(j + lane) * 3];
        a0 += xi * w[0];
        a1 += xi * w[1];
        a2 += xi * w[2];
    }
    #pragma unroll
    for (int off = 16; off > 0; off >>= 1) {
        a0 += __shfl_down_sync(0xffffffffu, a0, off);
        a1 += __shfl_down_sync(0xffffffffu, a1, off);
        a2 += __shfl_down_sync(0xffffffffu, a2, off);
    }
    if (lane == 0) {
        float s[3];
        s[0] = a0 + bg[0];
        s[1] = a1 + bg[1];
        s[2] = a2 + bg[2];
        #pragma unroll
        for (int e = 0; e < 3; e++) {
            float u = gu[(size_t)n * 3 + e];
            u = fminf(fmaxf(u, 1e-6f), 1.0f - 1e-6f);
            s[e] += -logf(-logf(u));
        }
        int best = 0;
        if (s[1] > s[best]) best = 1;
        if (s[2] > s[best]) best = 2;
        int pos = atomicAdd(&g_cursor[best], 1);
        g_idx[best * N_TOK + pos] = n;
    }
}

// ============================================================
// Kernel 2: split x into bf16 hi/lo
// ============================================================
__global__ void xsplit_kernel(const float* __restrict__ x) {
    size_t i = ((size_t)blockIdx.x * 256 + threadIdx.x) * 4;
    float4 v = *(const float4*)(x + i);
    bf16 h0 = __float2bfloat16_rn(v.x);
    bf16 h1 = __float2bfloat16_rn(v.y);
    bf16 h2 = __float2bfloat16_rn(v.z);
    bf16 h3 = __float2bfloat16_rn(v.w);
    bf16 l0 = __float2bfloat16_rn(v.x - __bfloat162float(h0));
    bf16 l1 = __float2bfloat16_rn(v.y - __bfloat162float(h1));
    bf16 l2 = __float2bfloat16_rn(v.z - __bfloat162float(h2));
    bf16 l3 = __float2bfloat16_rn(v.w - __bfloat162float(h3));
    __nv_bfloat162 ha = __halves2bfloat162(h0, h1), hb = __halves2bfloat162(h2, h3);
    __nv_bfloat162 la = __halves2bfloat162(l0, l1), lb = __halves2bfloat162(l2, l3);
    uint2 hq = make_uint2(*(uint32_t*)&ha, *(uint32_t*)&hb);
    uint2 lq = make_uint2(*(uint32_t*)&la, *(uint32_t*)&lb);
    *(uint2*)(g_xhi + i) = hq;
    *(uint2*)(g_xlo + i) = lq;
}

// ============================================================
// Kernel 3: transpose + split weights -> K-major bf16 hi/lo
// ============================================================
__global__ void wsplit_kernel(const float* __restrict__ W1,
                              const float* __restrict__ W3,
                              const float* __restrict__ W2) {
    __shared__ float t[32][33];
    int z = blockIdx.z;
    int mat = z / 3, e = z % 3;
    const float* src;
    bf16 *dh, *dl;
    if (mat == 0)      { src = W1; dh = g_w1hi; dl = g_w1lo; }
    else if (mat == 1) { src = W3; dh = g_w3hi; dl = g_w3lo; }
    else               { src = W2; dh = g_w2hi; dl = g_w2lo; }
    size_t eo = (size_t)e * HDIM * HDIM;
    src += eo; dh += eo; dl += eo;

    int bx = blockIdx.x * 32, by = blockIdx.y * 32;
    int tx = threadIdx.x;
    for (int i = threadIdx.y; i < 32; i += 8)
        t[i][tx] = src[(size_t)(by + i) * HDIM + bx + tx];
    __syncthreads();
    for (int i = threadIdx.y; i < 32; i += 8) {
        float v = t[tx][i];                              // = W[by+tx][bx+i]
        size_t di = (size_t)(bx + i) * HDIM + by + tx;   // Wt[h][d]
        bf16 h = __float2bfloat16_rn(v);
        dh[di] = h;
        dl[di] = __float2bfloat16_rn(v - __bfloat162float(h));
    }
}

// ============================================================
// Kernel 4: pass A — mma.sync dual GEMM (h1, h3) + activation
//   8 warps as 2m x 4n (warp tile 64x32), 4-stage cp.async,
//   software-pipelined fragments. grid (8, 512, 3)
// ============================================================
#define A_STAGE 49152
#define A_NST   4
#define A_SMEM  (2048 + A_NST * A_STAGE)

__global__ __launch_bounds__(256, 1)
void passA_mma(const float* __restrict__ b1, const float* __restrict__ b3) {
    int e    = blockIdx.z;
    int cnt  = g_cursor[e];
    int base = blockIdx.y * BM;
    if (base >= cnt) return;
    int n0  = blockIdx.x * BN;
    int tid = threadIdx.x, wid = tid >> 5, lane = tid & 31;
    int m64 = (wid & 1) * 64;        // warp m offset (2 m-groups)
    int n32 = (wid >> 1) * 32;       // warp n offset (4 n-groups)

    extern __shared__ char smem[];
    uint32_t sb = s2u(smem);

    int off = 0;
    for (int i = 0; i < e; i++) off += g_cursor[i];

    int*   srow = (int*)(smem);
    float* sb1  = (float*)(smem + 512);
    float* sb3  = (float*)(smem + 1024);
    if (tid < BM) {
        int p = base + tid;
        srow[tid] = (p < cnt) ? g_idx[e * N_TOK + p] : g_idx[e * N_TOK];
        sb1[tid]  = b1[e * HDIM + n0 + tid];
        sb3[tid]  = b3[e * HDIM + n0 + tid];
    }
    __syncthreads();

    const bf16* w1h = g_w1hi + (size_t)e * HDIM * HDIM;
    const bf16* w1l = g_w1lo + (size_t)e * HDIM * HDIM;
    const bf16* w3h = g_w3hi + (size_t)e * HDIM * HDIM;
    const bf16* w3l = g_w3lo + (size_t)e * HDIM * HDIM;

    // ---- hoisted gather addressing (loop-invariant) ----
    int    rr   = tid >> 3;
    int    cseg = (tid & 7) * 8;          // col within chunk
    size_t aoff[4], boff[4];
    uint32_t ssw[4];
    #pragma unroll
    for (int it = 0; it < 4; it++) {
        int row  = rr + 32 * it;
        aoff[it] = (size_t)srow[row] * HDIM;
        boff[it] = (size_t)(n0 + row) * HDIM;
        ssw[it]  = swz((uint32_t)((row << 7) | ((tid & 7) << 4)));
    }

    auto load_chunk = [&](int c) {
        int st  = c & (A_NST - 1);
        int kk0 = (c & 15) << 6;
        const bf16* As  = (c >= 16 && c < 32) ? g_xlo : g_xhi;
        const bf16* B1s = (c < 32) ? w1h : w1l;
        const bf16* B3s = (c < 32) ? w3h : w3l;
        uint32_t sa = sb + 2048 + st * A_STAGE;
        #pragma unroll
        for (int it = 0; it < 4; it++) {
            cp16(sa + ssw[it],         As  + aoff[it] + kk0 + cseg);
            cp16(sa + 16384 + ssw[it], B1s + boff[it] + kk0 + cseg);
            cp16(sa + 32768 + ssw[it], B3s + boff[it] + kk0 + cseg);
        }
        CP_COMMIT();
    };

    // ---- hoisted ldmatrix addressing ----
    int arow_lm = (lane & 15);            // + m64 + i*16
    int ahalf   = (lane >> 4);            // k half selector
    int nrow_lm = ((lane >> 4) << 3) + (lane & 7);
    int bhalf   = (lane >> 3) & 1;

    float acc1[4][4][4];
    float acc3[4][4][4];
    #pragma unroll
    for (int i = 0; i < 4; i++)
        #pragma unroll
        for (int j = 0; j < 4; j++)
            #pragma unroll
            for (int q = 0; q < 4; q++) { acc1[i][j][q] = 0.f; acc3[i][j][q] = 0.f; }

    load_chunk(0); load_chunk(1); load_chunk(2);

    for (int c = 0; c < NCH; c++) {
        CP_WAIT(2);
        __syncthreads();
        if (c + 3 < NCH) load_chunk(c + 3);
        else CP_COMMIT();                 // keep group count invariant for CP_WAIT(2)
        uint32_t sa = sb + 2048 + (c & (A_NST - 1)) * A_STAGE;

        uint32_t af[2][4][4];
        // preload A fragments for kk=0
        #pragma unroll
        for (int i = 0; i < 4; i++) {
            int row = m64 + i * 16 + arow_lm;
            uint32_t o = (uint32_t)(row * 128 + ahalf * 16);
            LDSM4(af[0][i][0], af[0][i][1], af[0][i][2], af[0][i][3], sa + swz(o));
        }

        #pragma unroll
        for (int kk = 0; kk < 4; kk++) {
            // batch-load all B1/B3 fragments for this kk
            uint32_t bfr[2][4], cfr[2][4];
            #pragma unroll
            for (int jj = 0; jj < 2; jj++) {
                int nrow = n32 + jj * 16 + nrow_lm;
                uint32_t sw = swz((uint32_t)(nrow * 128 + (kk * 2 + bhalf) * 16));
                LDSM4(bfr[jj][0], bfr[jj][1], bfr[jj][2], bfr[jj][3], sa + 16384 + sw);
                LDSM4(cfr[jj][0], cfr[jj][1], cfr[jj][2], cfr[jj][3], sa + 32768 + sw);
            }
            // prefetch next-kk A fragments (hides under the MMA burst)
            if (kk < 3) {
                #pragma unroll
                for (int i = 0; i < 4; i++) {
                    int row = m64 + i * 16 + arow_lm;
                    uint32_t o = (uint32_t)(row * 128 + ((kk + 1) * 2 + ahalf) * 16);
                    LDSM4(af[(kk + 1) & 1][i][0], af[(kk + 1) & 1][i][1],
                          af[(kk + 1) & 1][i][2], af[(kk + 1) & 1][i][3], sa + swz(o));
                }
            }
            uint32_t (*a)[4] = af[kk & 1];
            #pragma unroll
            for (int jj = 0; jj < 2; jj++)
                #pragma unroll
                for (int i = 0; i < 4; i++) {
                    MMA16816(acc1[i][2*jj],   a[i][0], a[i][1], a[i][2], a[i][3], bfr[jj][0], bfr[jj][1]);
                    MMA16816(acc1[i][2*jj+1], a[i][0], a[i][1], a[i][2], a[i][3], bfr[jj][2], bfr[jj][3]);
                    MMA16816(acc3[i][2*jj],   a[i][0], a[i][1], a[i][2], a[i][3], cfr[jj][0], cfr[jj][1]);
                    MMA16816(acc3[i][2*jj+1], a[i][0], a[i][1], a[i][2], a[i][3], cfr[jj][2], cfr[jj][3]);
                }
        }
    }

    // epilogue: bias + activation, split-bf16 store of inner
    int mrows = cnt - base; if (mrows > BM) mrows = BM;
    #pragma unroll
    for (int i = 0; i < 4; i++) {
        int r0 = m64 + i * 16 + (lane >> 2);
        int r1 = r0 + 8;
        size_t g0 = (size_t)(off + base + r0) * HDIM;
        size_t g1 = (size_t)(off + base + r1) * HDIM;
        #pragma unroll
        for (int j = 0; j < 4; j++) {
            int n = n32 + j * 8 + (lane & 3) * 2;
            float bb1a = sb1[n], bb1b = sb1[n + 1];
            float bb3a = sb3[n], bb3b = sb3[n + 1];
            if (r0 < mrows) {
                float v0 = act_fn(acc1[i][j][0] + bb1a, e) * (acc3[i][j][0] + bb3a);
                float v1 = act_fn(acc1[i][j][1] + bb1b, e) * (acc3[i][j][1] + bb3b);
                bf16 h0 = __float2bfloat16_rn(v0), h1 = __float2bfloat16_rn(v1);
                *(uint32_t*)(g_ihi + g0 + n0 + n) = pack_bf2(v0, v1);
                *(uint32_t*)(g_ilo + g0 + n0 + n) =
                    pack_bf2(v0 - __bfloat162float(h0), v1 - __bfloat162float(h1));
            }
            if (r1 < mrows) {
                float v2 = act_fn(acc1[i][j][2] + bb1a, e) * (acc3[i][j][2] + bb3a);
                float v3 = act_fn(acc1[i][j][3] + bb1b, e) * (acc3[i][j][3] + bb3b);
                bf16 h2 = __float2bfloat16_rn(v2), h3 = __float2bfloat16_rn(v3);
                *(uint32_t*)(g_ihi + g1 + n0 + n) = pack_bf2(v2, v3);
                *(uint32_t*)(g_ilo + g1 + n0 + n) =
                    pack_bf2(v2 - __bfloat162float(h2), v3 - __bfloat162float(h3));
            }
        }
    }
}

// ============================================================
// Kernel 5: pass B — mma.sync GEMM inner@W2 + b2, scatter
//   same structure, single accumulator. grid (8, 512, 3)
// ============================================================
#define B_STAGE 32768
#define B_NST   4
#define B_SMEM  (2048 + B_NST * B_STAGE)

__global__ __launch_bounds__(256, 1)
void passB_mma(const float* __restrict__ b2, float* __restrict__ out) {
    int e    = blockIdx.z;
    int cnt  = g_cursor[e];
    int base = blockIdx.y * BM;
    if (base >= cnt) return;
    int n0  = blockIdx.x * BN;
    int tid = threadIdx.x, wid = tid >> 5, lane = tid & 31;
    int m64 = (wid & 1) * 64;
    int n32 = (wid >> 1) * 32;

    extern __shared__ char smem[];
    uint32_t sb = s2u(smem);

    int off = 0;
    for (int i = 0; i < e; i++) off += g_cursor[i];

    int*   stok = (int*)(smem);
    float* sb2  = (float*)(smem + 512);
    if (tid < BM) {
        int p = base + tid;
        stok[tid] = (p < cnt) ? g_idx[e * N_TOK + p] : 0;
        sb2[tid]  = b2[e * HDIM + n0 + tid];
    }
    __syncthreads();

    const bf16* w2h = g_w2hi + (size_t)e * HDIM * HDIM;
    const bf16* w2l = g_w2lo + (size_t)e * HDIM * HDIM;

    int    rr   = tid >> 3;
    int    cseg = (tid & 7) * 8;
    size_t aoff[4], boff[4];
    uint32_t ssw[4];
    #pragma unroll
    for (int it = 0; it < 4; it++) {
        int row  = rr + 32 * it;
        int arow = (base + row < cnt) ? (off + base + row) : off;
        aoff[it] = (size_t)arow * HDIM;
        boff[it] = (size_t)(n0 + row) * HDIM;
        ssw[it]  = swz((uint32_t)((row << 7) | ((tid & 7) << 4)));
    }

    auto load_chunk = [&](int c) {
        int st  = c & (B_NST - 1);
        int kk0 = (c & 15) << 6;
        const bf16* As = (c >= 16 && c < 32) ? g_ilo : g_ihi;
        const bf16* Bs = (c < 32) ? w2h : w2l;
        uint32_t sa = sb + 2048 + st * B_STAGE;
        #pragma unroll
        for (int it = 0; it < 4; it++) {
            cp16(sa + ssw[it],         As + aoff[it] + kk0 + cseg);
            cp16(sa + 16384 + ssw[it], Bs + boff[it] + kk0 + cseg);
        }
        CP_COMMIT();
    };

    int arow_lm = (lane & 15);
    int ahalf   = (lane >> 4);
    int nrow_lm = ((lane >> 4) << 3) + (lane & 7);
    int bhalf   = (lane >> 3) & 1;

    float acc[4][4][4];
    #pragma unroll
    for (int i = 0; i < 4; i++)
        #pragma unroll
        for (int j = 0; j < 4; j++)
            #pragma unroll
            for (int q = 0; q < 4; q++) acc[i][j][q] = 0.f;

    load_chunk(0); load_chunk(1); load_chunk(2);

    for (int c = 0; c < NCH; c++) {
        CP_WAIT(2);
        __syncthreads();
        if (c + 3 < NCH) load_chunk(c + 3);
        else CP_COMMIT();
        uint32_t sa = sb + 2048 + (c & (B_NST - 1)) * B_STAGE;

        uint32_t af[2][4][4];
        #pragma unroll
        for (int i = 0; i < 4; i++) {
            int row = m64 + i * 16 + arow_lm;
            uint32_t o = (uint32_t)(row * 128 + ahalf * 16);
            LDSM4(af[0][i][0], af[0][i][1], af[0][i][2], af[0][i][3], sa + swz(o));
        }

        #pragma unroll
        for (int kk = 0; kk < 4; kk++) {
            uint32_t bfr[2][4];
            #pragma unroll
            for (int jj = 0; jj < 2; jj++) {
                int nrow = n32 + jj * 16 + nrow_lm;
                uint32_t sw = swz((uint32_t)(nrow * 128 + (kk * 2 + bhalf) * 16));
                LDSM4(bfr[jj][0], bfr[jj][1], bfr[jj][2], bfr[jj][3], sa + 16384 + sw);
            }
            if (kk < 3) {
                #pragma unroll
                for (int i = 0; i < 4; i++) {
                    int row = m64 + i * 16 + arow_lm;
                    uint32_t o = (uint32_t)(row * 128 + ((kk + 1) * 2 + ahalf) * 16);
                    LDSM4(af[(kk + 1) & 1][i][0], af[(kk + 1) & 1][i][1],
                          af[(kk + 1) & 1][i][2], af[(kk + 1) & 1][i][3], sa + swz(o));
                }
            }
            uint32_t (*a)[4] = af[kk & 1];
            #pragma unroll
            for (int jj = 0; jj < 2; jj++)
                #pragma unroll
                for (int i = 0; i < 4; i++) {
                    MMA16816(acc[i][2*jj],   a[i][0], a[i][1], a[i][2], a[i][3], bfr[jj][0], bfr[jj][1]);
                    MMA16816(acc[i][2*jj+1], a[i][0], a[i][1], a[i][2], a[i][3], bfr[jj][2], bfr[jj][3]);
                }
        }
    }

    int mrows = cnt - base; if (mrows > BM) mrows = BM;
    #pragma unroll
    for (int i = 0; i < 4; i++) {
        int r0 = m64 + i * 16 + (lane >> 2);
        int r1 = r0 + 8;
        float* d0 = out + (size_t)stok[r0] * HDIM + n0;
        float* d1 = out + (size_t)stok[r1 < BM ? r1 : 0] * HDIM + n0;
        #pragma unroll
        for (int j = 0; j < 4; j++) {
            int n = n32 + j * 8 + (lane & 3) * 2;
            float ba = sb2[n], bb = sb2[n + 1];
            if (r0 < mrows) {
                float2 o0 = make_float2(acc[i][j][0] + ba, acc[i][j][1] + bb);
                *(float2*)(d0 + n) = o0;
            }
            if (r1 < mrows) {
                float2 o1 = make_float2(acc[i][j][2] + ba, acc[i][j][3] + bb);
                *(float2*)(d1 + n) = o1;
            }
        }
    }
}

// ============================================================
extern "C" void kernel_launch(void* const* d_in, const int* in_sizes, int n_in,
                              void* d_out, int out_size) {
    (void)in_sizes; (void)n_in; (void)out_size;
    const float* x  = (const float*)d_in[0];
    const float* W1 = (const float*)d_in[1];
    const float* b1 = (const float*)d_in[2];
    const float* W2 = (const float*)d_in[3];
    const float* b2 = (const float*)d_in[4];
    const float* W3 = (const float*)d_in[5];
    const float* b3 = (const float*)d_in[6];
    const float* Wg = (const float*)d_in[7];
    const float* bg = (const float*)d_in[8];
    const float* gu = (const float*)d_in[9];
    float* out = (float*)d_out;

    cudaFuncSetAttribute(passA_mma, cudaFuncAttributeMaxDynamicSharedMemorySize, A_SMEM);
    cudaFuncSetAttribute(passB_mma, cudaFuncAttributeMaxDynamicSharedMemorySize, B_SMEM);

    zero_kernel<<<1, 32>>>();
    gate_kernel<<<N_TOK / 8, 256>>>(x, Wg, bg, gu);
    xsplit_kernel<<<(int)(((size_t)N_TOK * HDIM) / 1024), 256>>>(x);
    {
        dim3 g(32, 32, 9), b(32, 8);
        wsplit_kernel<<<g, b>>>(W1, W3, W2);
    }
    {
        dim3 grid(HDIM / BN, N_TOK / BM, NEXP);
        passA_mma<<<grid, 256, A_SMEM>>>(b1, b3);
        passB_mma<<<grid, 256, B_SMEM>>>(b2, out);
    }
}

// round 9
// speedup vs baseline: 1.0285x; 1.0285x over previous
#include <cuda_runtime.h>
#include <cuda_bf16.h>
#include <math.h>
#include <stdint.h>

#define N_TOK 65536
#define HDIM  1024
#define NEXP  3
#define NCH   48          // 3*1024/64 : K-concat chunks (hi*hi, lo*hi, hi*lo)
#define BM    128
#define BN    128

typedef __nv_bfloat16 bf16;

// ------------------- scratch (allocation-free) -------------------
__device__ int  g_cursor[NEXP];
__device__ int  g_idx[NEXP * N_TOK];
__device__ bf16 g_xhi[(size_t)N_TOK * HDIM];
__device__ bf16 g_xlo[(size_t)N_TOK * HDIM];
__device__ bf16 g_ihi[(size_t)N_TOK * HDIM];
__device__ bf16 g_ilo[(size_t)N_TOK * HDIM];
__device__ bf16 g_w1hi[(size_t)NEXP * HDIM * HDIM];
__device__ bf16 g_w1lo[(size_t)NEXP * HDIM * HDIM];
__device__ bf16 g_w3hi[(size_t)NEXP * HDIM * HDIM];
__device__ bf16 g_w3lo[(size_t)NEXP * HDIM * HDIM];
__device__ bf16 g_w2hi[(size_t)NEXP * HDIM * HDIM];
__device__ bf16 g_w2lo[(size_t)NEXP * HDIM * HDIM];

// ------------------- helpers -------------------
__device__ __forceinline__ uint32_t s2u(const void* p) {
    return (uint32_t)__cvta_generic_to_shared(p);
}
__device__ __forceinline__ void cp16(uint32_t dst, const void* src) {
    asm volatile("cp.async.cg.shared.global [%0], [%1], 16;" :: "r"(dst), "l"(src));
}
#define CP_COMMIT() asm volatile("cp.async.commit_group;" ::: "memory")
#define CP_WAIT(n)  asm volatile("cp.async.wait_group %0;" :: "n"(n) : "memory")

#define LDSM4(r0,r1,r2,r3,addr) \
    asm volatile("ldmatrix.sync.aligned.m8n8.x4.shared.b16 {%0,%1,%2,%3}, [%4];" \
        : "=r"(r0), "=r"(r1), "=r"(r2), "=r"(r3) : "r"(addr))

#define MMA16816(d, a0,a1,a2,a3, b0,b1) \
    asm volatile("mma.sync.aligned.m16n8k16.row.col.f32.bf16.bf16.f32 " \
        "{%0,%1,%2,%3}, {%4,%5,%6,%7}, {%8,%9}, {%0,%1,%2,%3};" \
        : "+f"((d)[0]), "+f"((d)[1]), "+f"((d)[2]), "+f"((d)[3]) \
        : "r"(a0), "r"(a1), "r"(a2), "r"(a3), "r"(b0), "r"(b1))

__device__ __forceinline__ uint32_t swz(uint32_t o) { return o ^ ((o >> 3) & 0x70); }

__device__ __forceinline__ float act_fn(float h1, int e) {
    if (e == 0) return h1 / (1.0f + __expf(-h1));
    if (e == 1) return 0.5f * h1 * (1.0f + erff(h1 * 0.70710678118654752f));
    return fmaxf(h1, 0.0f);
}
__device__ __forceinline__ uint32_t pack_bf2(float a, float b) {
    __nv_bfloat162 t = __halves2bfloat162(__float2bfloat16_rn(a), __float2bfloat16_rn(b));
    return *(uint32_t*)&t;
}

// ============================================================
// Kernel 0: zero per-expert cursors
// ============================================================
__global__ void zero_kernel() {
    if (threadIdx.x < NEXP) g_cursor[threadIdx.x] = 0;
}

// ============================================================
// Kernel 1: gating (one warp per token)
// ============================================================
__global__ void gate_kernel(const float* __restrict__ x,
                            const float* __restrict__ Wg,
                            const float* __restrict__ bg,
                            const float* __restrict__ gu) {
    __shared__ float sWg[HDIM * NEXP];
    int tid = threadIdx.x;
    for (int t = tid; t < HDIM * NEXP; t += blockDim.x) sWg[t] = Wg[t];
    __syncthreads();

    int warp = tid >> 5, lane = tid & 31;
    int n = blockIdx.x * 8 + warp;
    const float* xr = x + (size_t)n * HDIM;

    float a0 = 0.f, a1 = 0.f, a2 = 0.f;
    #pragma unroll 8
    for (int j = 0; j < HDIM; j += 32) {
        float xi = xr[j + lane];
        const float* w = &sWg[(j + lane) * 3];
        a0 += xi * w[0];
        a1 += xi * w[1];
        a2 += xi * w[2];
    }
    #pragma unroll
    for (int off = 16; off > 0; off >>= 1) {
        a0 += __shfl_down_sync(0xffffffffu, a0, off);
        a1 += __shfl_down_sync(0xffffffffu, a1, off);
        a2 += __shfl_down_sync(0xffffffffu, a2, off);
    }
    if (lane == 0) {
        float s[3];
        s[0] = a0 + bg[0];
        s[1] = a1 + bg[1];
        s[2] = a2 + bg[2];
        #pragma unroll
        for (int e = 0; e < 3; e++) {
            float u = gu[(size_t)n * 3 + e];
            u = fminf(fmaxf(u, 1e-6f), 1.0f - 1e-6f);
            s[e] += -logf(-logf(u));
        }
        int best = 0;
        if (s[1] > s[best]) best = 1;
        if (s[2] > s[best]) best = 2;
        int pos = atomicAdd(&g_cursor[best], 1);
        g_idx[best * N_TOK + pos] = n;
    }
}

// ============================================================
// Kernel 2: split x into bf16 hi/lo
// ============================================================
__global__ void xsplit_kernel(const float* __restrict__ x) {
    size_t i = ((size_t)blockIdx.x * 256 + threadIdx.x) * 4;
    float4 v = *(const float4*)(x + i);
    bf16 h0 = __float2bfloat16_rn(v.x);
    bf16 h1 = __float2bfloat16_rn(v.y);
    bf16 h2 = __float2bfloat16_rn(v.z);
    bf16 h3 = __float2bfloat16_rn(v.w);
    bf16 l0 = __float2bfloat16_rn(v.x - __bfloat162float(h0));
    bf16 l1 = __float2bfloat16_rn(v.y - __bfloat162float(h1));
    bf16 l2 = __float2bfloat16_rn(v.z - __bfloat162float(h2));
    bf16 l3 = __float2bfloat16_rn(v.w - __bfloat162float(h3));
    __nv_bfloat162 ha = __halves2bfloat162(h0, h1), hb = __halves2bfloat162(h2, h3);
    __nv_bfloat162 la = __halves2bfloat162(l0, l1), lb = __halves2bfloat162(l2, l3);
    uint2 hq = make_uint2(*(uint32_t*)&ha, *(uint32_t*)&hb);
    uint2 lq = make_uint2(*(uint32_t*)&la, *(uint32_t*)&lb);
    *(uint2*)(g_xhi + i) = hq;
    *(uint2*)(g_xlo + i) = lq;
}

// ============================================================
// Kernel 3: transpose + split weights -> K-major bf16 hi/lo
// ============================================================
__global__ void wsplit_kernel(const float* __restrict__ W1,
                              const float* __restrict__ W3,
                              const float* __restrict__ W2) {
    __shared__ float t[32][33];
    int z = blockIdx.z;
    int mat = z / 3, e = z % 3;
    const float* src;
    bf16 *dh, *dl;
    if (mat == 0)      { src = W1; dh = g_w1hi; dl = g_w1lo; }
    else if (mat == 1) { src = W3; dh = g_w3hi; dl = g_w3lo; }
    else               { src = W2; dh = g_w2hi; dl = g_w2lo; }
    size_t eo = (size_t)e * HDIM * HDIM;
    src += eo; dh += eo; dl += eo;

    int bx = blockIdx.x * 32, by = blockIdx.y * 32;
    int tx = threadIdx.x;
    for (int i = threadIdx.y; i < 32; i += 8)
        t[i][tx] = src[(size_t)(by + i) * HDIM + bx + tx];
    __syncthreads();
    for (int i = threadIdx.y; i < 32; i += 8) {
        float v = t[tx][i];                              // = W[by+tx][bx+i]
        size_t di = (size_t)(bx + i) * HDIM + by + tx;   // Wt[h][d]
        bf16 h = __float2bfloat16_rn(v);
        dh[di] = h;
        dl[di] = __float2bfloat16_rn(v - __bfloat162float(h));
    }
}

// ============================================================
// Kernel 4: pass A — mma.sync dual GEMM (h1, h3) + activation
//   512 threads, 16 warps as 4m x 4n (warp tile 32x32),
//   4-stage cp.async. grid (8, 512, 3)
// ============================================================
#define A_STAGE 49152
#define A_NST   4
#define A_SMEM  (2048 + A_NST * A_STAGE)

__global__ __launch_bounds__(512, 1)
void passA_mma(const float* __restrict__ b1, const float* __restrict__ b3) {
    int e    = blockIdx.z;
    int cnt  = g_cursor[e];
    int base = blockIdx.y * BM;
    if (base >= cnt) return;
    int n0  = blockIdx.x * BN;
    int tid = threadIdx.x, wid = tid >> 5, lane = tid & 31;
    int m32 = (wid & 3) * 32;        // warp m offset (4 m-groups)
    int n32 = (wid >> 2) * 32;       // warp n offset (4 n-groups)

    extern __shared__ char smem[];
    uint32_t sb = s2u(smem);

    int off = 0;
    for (int i = 0; i < e; i++) off += g_cursor[i];

    int*   srow = (int*)(smem);
    float* sb1  = (float*)(smem + 512);
    float* sb3  = (float*)(smem + 1024);
    if (tid < BM) {
        int p = base + tid;
        srow[tid] = (p < cnt) ? g_idx[e * N_TOK + p] : g_idx[e * N_TOK];
        sb1[tid]  = b1[e * HDIM + n0 + tid];
        sb3[tid]  = b3[e * HDIM + n0 + tid];
    }
    __syncthreads();

    const bf16* w1h = g_w1hi + (size_t)e * HDIM * HDIM;
    const bf16* w1l = g_w1lo + (size_t)e * HDIM * HDIM;
    const bf16* w3h = g_w3hi + (size_t)e * HDIM * HDIM;
    const bf16* w3l = g_w3lo + (size_t)e * HDIM * HDIM;

    // ---- hoisted gather addressing (loop-invariant); 512 threads: 2 rows each
    int    rr   = tid >> 3;               // 0..63
    int    cseg = (tid & 7) * 8;          // col within chunk
    size_t aoff[2], boff[2];
    uint32_t ssw[2];
    #pragma unroll
    for (int it = 0; it < 2; it++) {
        int row  = rr + 64 * it;
        aoff[it] = (size_t)srow[row] * HDIM;
        boff[it] = (size_t)(n0 + row) * HDIM;
        ssw[it]  = swz((uint32_t)((row << 7) | ((tid & 7) << 4)));
    }

    auto load_chunk = [&](int c) {
        int st  = c & (A_NST - 1);
        int kk0 = (c & 15) << 6;
        const bf16* As  = (c >= 16 && c < 32) ? g_xlo : g_xhi;
        const bf16* B1s = (c < 32) ? w1h : w1l;
        const bf16* B3s = (c < 32) ? w3h : w3l;
        uint32_t sa = sb + 2048 + st * A_STAGE;
        #pragma unroll
        for (int it = 0; it < 2; it++) {
            cp16(sa + ssw[it],         As  + aoff[it] + kk0 + cseg);
            cp16(sa + 16384 + ssw[it], B1s + boff[it] + kk0 + cseg);
            cp16(sa + 32768 + ssw[it], B3s + boff[it] + kk0 + cseg);
        }
        CP_COMMIT();
    };

    // ---- hoisted ldmatrix addressing ----
    int arow_lm = (lane & 15);
    int ahalf   = (lane >> 4);
    int nrow_lm = ((lane >> 4) << 3) + (lane & 7);
    int bhalf   = (lane >> 3) & 1;

    float acc1[2][4][4];
    float acc3[2][4][4];
    #pragma unroll
    for (int i = 0; i < 2; i++)
        #pragma unroll
        for (int j = 0; j < 4; j++)
            #pragma unroll
            for (int q = 0; q < 4; q++) { acc1[i][j][q] = 0.f; acc3[i][j][q] = 0.f; }

    load_chunk(0); load_chunk(1); load_chunk(2);

    for (int c = 0; c < NCH; c++) {
        CP_WAIT(2);
        __syncthreads();
        if (c + 3 < NCH) load_chunk(c + 3);
        else CP_COMMIT();                 // keep group count invariant for CP_WAIT(2)
        uint32_t sa = sb + 2048 + (c & (A_NST - 1)) * A_STAGE;
        #pragma unroll
        for (int kk = 0; kk < 4; kk++) {
            uint32_t a[2][4];
            #pragma unroll
            for (int i = 0; i < 2; i++) {
                int row = m32 + i * 16 + arow_lm;
                uint32_t o = (uint32_t)(row * 128 + (kk * 2 + ahalf) * 16);
                LDSM4(a[i][0], a[i][1], a[i][2], a[i][3], sa + swz(o));
            }
            #pragma unroll
            for (int jj = 0; jj < 2; jj++) {
                int nrow = n32 + jj * 16 + nrow_lm;
                uint32_t sw = swz((uint32_t)(nrow * 128 + (kk * 2 + bhalf) * 16));
                uint32_t b0, b1r, b2r, b3r, c0, c1r, c2r, c3r;
                LDSM4(b0, b1r, b2r, b3r, sa + 16384 + sw);
                LDSM4(c0, c1r, c2r, c3r, sa + 32768 + sw);
                #pragma unroll
                for (int i = 0; i < 2; i++) {
                    MMA16816(acc1[i][2*jj],   a[i][0], a[i][1], a[i][2], a[i][3], b0, b1r);
                    MMA16816(acc1[i][2*jj+1], a[i][0], a[i][1], a[i][2], a[i][3], b2r, b3r);
                    MMA16816(acc3[i][2*jj],   a[i][0], a[i][1], a[i][2], a[i][3], c0, c1r);
                    MMA16816(acc3[i][2*jj+1], a[i][0], a[i][1], a[i][2], a[i][3], c2r, c3r);
                }
            }
        }
    }

    // epilogue: bias + activation, split-bf16 store of inner
    int mrows = cnt - base; if (mrows > BM) mrows = BM;
    #pragma unroll
    for (int i = 0; i < 2; i++) {
        int r0 = m32 + i * 16 + (lane >> 2);
        int r1 = r0 + 8;
        size_t g0 = (size_t)(off + base + r0) * HDIM;
        size_t g1 = (size_t)(off + base + r1) * HDIM;
        #pragma unroll
        for (int j = 0; j < 4; j++) {
            int n = n32 + j * 8 + (lane & 3) * 2;
            float bb1a = sb1[n], bb1b = sb1[n + 1];
            float bb3a = sb3[n], bb3b = sb3[n + 1];
            if (r0 < mrows) {
                float v0 = act_fn(acc1[i][j][0] + bb1a, e) * (acc3[i][j][0] + bb3a);
                float v1 = act_fn(acc1[i][j][1] + bb1b, e) * (acc3[i][j][1] + bb3b);
                bf16 h0 = __float2bfloat16_rn(v0), h1 = __float2bfloat16_rn(v1);
                *(uint32_t*)(g_ihi + g0 + n0 + n) = pack_bf2(v0, v1);
                *(uint32_t*)(g_ilo + g0 + n0 + n) =
                    pack_bf2(v0 - __bfloat162float(h0), v1 - __bfloat162float(h1));
            }
            if (r1 < mrows) {
                float v2 = act_fn(acc1[i][j][2] + bb1a, e) * (acc3[i][j][2] + bb3a);
                float v3 = act_fn(acc1[i][j][3] + bb1b, e) * (acc3[i][j][3] + bb3b);
                bf16 h2 = __float2bfloat16_rn(v2), h3 = __float2bfloat16_rn(v3);
                *(uint32_t*)(g_ihi + g1 + n0 + n) = pack_bf2(v2, v3);
                *(uint32_t*)(g_ilo + g1 + n0 + n) =
                    pack_bf2(v2 - __bfloat162float(h2), v3 - __bfloat162float(h3));
            }
        }
    }
}

// ============================================================
// Kernel 5: pass B — mma.sync GEMM inner@W2 + b2, scatter
//   512 threads, 4m x 4n. grid (8, 512, 3)
// ============================================================
#define B_STAGE 32768
#define B_NST   4
#define B_SMEM  (2048 + B_NST * B_STAGE)

__global__ __launch_bounds__(512, 1)
void passB_mma(const float* __restrict__ b2, float* __restrict__ out) {
    int e    = blockIdx.z;
    int cnt  = g_cursor[e];
    int base = blockIdx.y * BM;
    if (base >= cnt) return;
    int n0  = blockIdx.x * BN;
    int tid = threadIdx.x, wid = tid >> 5, lane = tid & 31;
    int m32 = (wid & 3) * 32;
    int n32 = (wid >> 2) * 32;

    extern __shared__ char smem[];
    uint32_t sb = s2u(smem);

    int off = 0;
    for (int i = 0; i < e; i++) off += g_cursor[i];

    int*   stok = (int*)(smem);
    float* sb2  = (float*)(smem + 512);
    if (tid < BM) {
        int p = base + tid;
        stok[tid] = (p < cnt) ? g_idx[e * N_TOK + p] : 0;
        sb2[tid]  = b2[e * HDIM + n0 + tid];
    }
    __syncthreads();

    const bf16* w2h = g_w2hi + (size_t)e * HDIM * HDIM;
    const bf16* w2l = g_w2lo + (size_t)e * HDIM * HDIM;

    int    rr   = tid >> 3;
    int    cseg = (tid & 7) * 8;
    size_t aoff[2], boff[2];
    uint32_t ssw[2];
    #pragma unroll
    for (int it = 0; it < 2; it++) {
        int row  = rr + 64 * it;
        int arow = (base + row < cnt) ? (off + base + row) : off;
        aoff[it] = (size_t)arow * HDIM;
        boff[it] = (size_t)(n0 + row) * HDIM;
        ssw[it]  = swz((uint32_t)((row << 7) | ((tid & 7) << 4)));
    }

    auto load_chunk = [&](int c) {
        int st  = c & (B_NST - 1);
        int kk0 = (c & 15) << 6;
        const bf16* As = (c >= 16 && c < 32) ? g_ilo : g_ihi;
        const bf16* Bs = (c < 32) ? w2h : w2l;
        uint32_t sa = sb + 2048 + st * B_STAGE;
        #pragma unroll
        for (int it = 0; it < 2; it++) {
            cp16(sa + ssw[it],         As + aoff[it] + kk0 + cseg);
            cp16(sa + 16384 + ssw[it], Bs + boff[it] + kk0 + cseg);
        }
        CP_COMMIT();
    };

    int arow_lm = (lane & 15);
    int ahalf   = (lane >> 4);
    int nrow_lm = ((lane >> 4) << 3) + (lane & 7);
    int bhalf   = (lane >> 3) & 1;

    float acc[2][4][4];
    #pragma unroll
    for (int i = 0; i < 2; i++)
        #pragma unroll
        for (int j = 0; j < 4; j++)
            #pragma unroll
            for (int q = 0; q < 4; q++) acc[i][j][q] = 0.f;

    load_chunk(0); load_chunk(1); load_chunk(2);

    for (int c = 0; c < NCH; c++) {
        CP_WAIT(2);
        __syncthreads();
        if (c + 3 < NCH) load_chunk(c + 3);
        else CP_COMMIT();
        uint32_t sa = sb + 2048 + (c & (B_NST - 1)) * B_STAGE;
        #pragma unroll
        for (int kk = 0; kk < 4; kk++) {
            uint32_t a[2][4];
            #pragma unroll
            for (int i = 0; i < 2; i++) {
                int row = m32 + i * 16 + arow_lm;
                uint32_t o = (uint32_t)(row * 128 + (kk * 2 + ahalf) * 16);
                LDSM4(a[i][0], a[i][1], a[i][2], a[i][3], sa + swz(o));
            }
            #pragma unroll
            for (int jj = 0; jj < 2; jj++) {
                int nrow = n32 + jj * 16 + nrow_lm;
                uint32_t sw = swz((uint32_t)(nrow * 128 + (kk * 2 + bhalf) * 16));
                uint32_t b0, b1r, b2r, b3r;
                LDSM4(b0, b1r, b2r, b3r, sa + 16384 + sw);
                #pragma unroll
                for (int i = 0; i < 2; i++) {
                    MMA16816(acc[i][2*jj],   a[i][0], a[i][1], a[i][2], a[i][3], b0, b1r);
                    MMA16816(acc[i][2*jj+1], a[i][0], a[i][1], a[i][2], a[i][3], b2r, b3r);
                }
            }
        }
    }

    int mrows = cnt - base; if (mrows > BM) mrows = BM;
    #pragma unroll
    for (int i = 0; i < 2; i++) {
        int r0 = m32 + i * 16 + (lane >> 2);
        int r1 = r0 + 8;
        float* d0 = out + (size_t)stok[r0] * HDIM + n0;
        float* d1 = out + (size_t)stok[r1 < BM ? r1 : 0] * HDIM + n0;
        #pragma unroll
        for (int j = 0; j < 4; j++) {
            int n = n32 + j * 8 + (lane & 3) * 2;
            float ba = sb2[n], bb = sb2[n + 1];
            if (r0 < mrows) {
                float2 o0 = make_float2(acc[i][j][0] + ba, acc[i][j][1] + bb);
                *(float2*)(d0 + n) = o0;
            }
            if (r1 < mrows) {
                float2 o1 = make_float2(acc[i][j][2] + ba, acc[i][j][3] + bb);
                *(float2*)(d1 + n) = o1;
            }
        }
    }
}

// ============================================================
extern "C" void kernel_launch(void* const* d_in, const int* in_sizes, int n_in,
                              void* d_out, int out_size) {
    (void)in_sizes; (void)n_in; (void)out_size;
    const float* x  = (const float*)d_in[0];
    const float* W1 = (const float*)d_in[1];
    const float* b1 = (const float*)d_in[2];
    const float* W2 = (const float*)d_in[3];
    const float* b2 = (const float*)d_in[4];
    const float* W3 = (const float*)d_in[5];
    const float* b3 = (const float*)d_in[6];
    const float* Wg = (const float*)d_in[7];
    const float* bg = (const float*)d_in[8];
    const float* gu = (const float*)d_in[9];
    float* out = (float*)d_out;

    cudaFuncSetAttribute(passA_mma, cudaFuncAttributeMaxDynamicSharedMemorySize, A_SMEM);
    cudaFuncSetAttribute(passB_mma, cudaFuncAttributeMaxDynamicSharedMemorySize, B_SMEM);

    zero_kernel<<<1, 32>>>();
    gate_kernel<<<N_TOK / 8, 256>>>(x, Wg, bg, gu);
    xsplit_kernel<<<(int)(((size_t)N_TOK * HDIM) / 1024), 256>>>(x);
    {
        dim3 g(32, 32, 9), b(32, 8);
        wsplit_kernel<<<g, b>>>(W1, W3, W2);
    }
    {
        dim3 grid(HDIM / BN, N_TOK / BM, NEXP);
        passA_mma<<<grid, 512, A_SMEM>>>(b1, b3);
        passB_mma<<<grid, 512, B_SMEM>>>(b2, out);
    }
}

// round 10
// speedup vs baseline: 1.1202x; 1.0891x over previous
#include <cuda_runtime.h>
#include <cuda_bf16.h>
#include <math.h>
#include <stdint.h>

#define N_TOK 65536
#define HDIM  1024
#define NEXP  3
#define NCH   48          // 3*1024/64 : K-concat chunks (hi*hi, lo*hi, hi*lo)
#define BM    128
#define BN    64

typedef __nv_bfloat16 bf16;

// ------------------- scratch (allocation-free) -------------------
__device__ int  g_cursor[NEXP];
__device__ int  g_idx[NEXP * N_TOK];
__device__ bf16 g_xhi[(size_t)N_TOK * HDIM];
__device__ bf16 g_xlo[(size_t)N_TOK * HDIM];
__device__ bf16 g_ihi[(size_t)N_TOK * HDIM];
__device__ bf16 g_ilo[(size_t)N_TOK * HDIM];
__device__ bf16 g_w1hi[(size_t)NEXP * HDIM * HDIM];
__device__ bf16 g_w1lo[(size_t)NEXP * HDIM * HDIM];
__device__ bf16 g_w3hi[(size_t)NEXP * HDIM * HDIM];
__device__ bf16 g_w3lo[(size_t)NEXP * HDIM * HDIM];
__device__ bf16 g_w2hi[(size_t)NEXP * HDIM * HDIM];
__device__ bf16 g_w2lo[(size_t)NEXP * HDIM * HDIM];

// ------------------- helpers -------------------
__device__ __forceinline__ uint32_t s2u(const void* p) {
    return (uint32_t)__cvta_generic_to_shared(p);
}
__device__ __forceinline__ void cp16(uint32_t dst, const void* src) {
    asm volatile("cp.async.cg.shared.global [%0], [%1], 16;" :: "r"(dst), "l"(src));
}
#define CP_COMMIT() asm volatile("cp.async.commit_group;" ::: "memory")
#define CP_WAIT(n)  asm volatile("cp.async.wait_group %0;" :: "n"(n) : "memory")

#define LDSM4(r0,r1,r2,r3,addr) \
    asm volatile("ldmatrix.sync.aligned.m8n8.x4.shared.b16 {%0,%1,%2,%3}, [%4];" \
        : "=r"(r0), "=r"(r1), "=r"(r2), "=r"(r3) : "r"(addr))

#define MMA16816(d, a0,a1,a2,a3, b0,b1) \
    asm volatile("mma.sync.aligned.m16n8k16.row.col.f32.bf16.bf16.f32 " \
        "{%0,%1,%2,%3}, {%4,%5,%6,%7}, {%8,%9}, {%0,%1,%2,%3};" \
        : "+f"((d)[0]), "+f"((d)[1]), "+f"((d)[2]), "+f"((d)[3]) \
        : "r"(a0), "r"(a1), "r"(a2), "r"(a3), "r"(b0), "r"(b1))

__device__ __forceinline__ uint32_t swz(uint32_t o) { return o ^ ((o >> 3) & 0x70); }

__device__ __forceinline__ float act_fn(float h1, int e) {
    if (e == 0) return h1 / (1.0f + __expf(-h1));
    if (e == 1) return 0.5f * h1 * (1.0f + erff(h1 * 0.70710678118654752f));
    return fmaxf(h1, 0.0f);
}
__device__ __forceinline__ uint32_t pack_bf2(float a, float b) {
    __nv_bfloat162 t = __halves2bfloat162(__float2bfloat16_rn(a), __float2bfloat16_rn(b));
    return *(uint32_t*)&t;
}

// ============================================================
// Kernel 0: zero per-expert cursors
// ============================================================
__global__ void zero_kernel() {
    if (threadIdx.x < NEXP) g_cursor[threadIdx.x] = 0;
}

// ============================================================
// Kernel 1: gating (one warp per token)
// ============================================================
__global__ void gate_kernel(const float* __restrict__ x,
                            const float* __restrict__ Wg,
                            const float* __restrict__ bg,
                            const float* __restrict__ gu) {
    __shared__ float sWg[HDIM * NEXP];
    int tid = threadIdx.x;
    for (int t = tid; t < HDIM * NEXP; t += blockDim.x) sWg[t] = Wg[t];
    __syncthreads();

    int warp = tid >> 5, lane = tid & 31;
    int n = blockIdx.x * 8 + warp;
    const float* xr = x + (size_t)n * HDIM;

    float a0 = 0.f, a1 = 0.f, a2 = 0.f;
    #pragma unroll 8
    for (int j = 0; j < HDIM; j += 32) {
        float xi = xr[j + lane];
        const float* w = &sWg[(j + lane) * 3];
        a0 += xi * w[0];
        a1 += xi * w[1];
        a2 += xi * w[2];
    }
    #pragma unroll
    for (int off = 16; off > 0; off >>= 1) {
        a0 += __shfl_down_sync(0xffffffffu, a0, off);
        a1 += __shfl_down_sync(0xffffffffu, a1, off);
        a2 += __shfl_down_sync(0xffffffffu, a2, off);
    }
    if (lane == 0) {
        float s[3];
        s[0] = a0 + bg[0];
        s[1] = a1 + bg[1];
        s[2] = a2 + bg[2];
        #pragma unroll
        for (int e = 0; e < 3; e++) {
            float u = gu[(size_t)n * 3 + e];
            u = fminf(fmaxf(u, 1e-6f), 1.0f - 1e-6f);
            s[e] += -logf(-logf(u));
        }
        int best = 0;
        if (s[1] > s[best]) best = 1;
        if (s[2] > s[best]) best = 2;
        int pos = atomicAdd(&g_cursor[best], 1);
        g_idx[best * N_TOK + pos] = n;
    }
}

// ============================================================
// Kernel 2: split x into bf16 hi/lo
// ============================================================
__global__ void xsplit_kernel(const float* __restrict__ x) {
    size_t i = ((size_t)blockIdx.x * 256 + threadIdx.x) * 4;
    float4 v = *(const float4*)(x + i);
    bf16 h0 = __float2bfloat16_rn(v.x);
    bf16 h1 = __float2bfloat16_rn(v.y);
    bf16 h2 = __float2bfloat16_rn(v.z);
    bf16 h3 = __float2bfloat16_rn(v.w);
    bf16 l0 = __float2bfloat16_rn(v.x - __bfloat162float(h0));
    bf16 l1 = __float2bfloat16_rn(v.y - __bfloat162float(h1));
    bf16 l2 = __float2bfloat16_rn(v.z - __bfloat162float(h2));
    bf16 l3 = __float2bfloat16_rn(v.w - __bfloat162float(h3));
    __nv_bfloat162 ha = __halves2bfloat162(h0, h1), hb = __halves2bfloat162(h2, h3);
    __nv_bfloat162 la = __halves2bfloat162(l0, l1), lb = __halves2bfloat162(l2, l3);
    uint2 hq = make_uint2(*(uint32_t*)&ha, *(uint32_t*)&hb);
    uint2 lq = make_uint2(*(uint32_t*)&la, *(uint32_t*)&lb);
    *(uint2*)(g_xhi + i) = hq;
    *(uint2*)(g_xlo + i) = lq;
}

// ============================================================
// Kernel 3: transpose + split weights -> K-major bf16 hi/lo
// ============================================================
__global__ void wsplit_kernel(const float* __restrict__ W1,
                              const float* __restrict__ W3,
                              const float* __restrict__ W2) {
    __shared__ float t[32][33];
    int z = blockIdx.z;
    int mat = z / 3, e = z % 3;
    const float* src;
    bf16 *dh, *dl;
    if (mat == 0)      { src = W1; dh = g_w1hi; dl = g_w1lo; }
    else if (mat == 1) { src = W3; dh = g_w3hi; dl = g_w3lo; }
    else               { src = W2; dh = g_w2hi; dl = g_w2lo; }
    size_t eo = (size_t)e * HDIM * HDIM;
    src += eo; dh += eo; dl += eo;

    int bx = blockIdx.x * 32, by = blockIdx.y * 32;
    int tx = threadIdx.x;
    for (int i = threadIdx.y; i < 32; i += 8)
        t[i][tx] = src[(size_t)(by + i) * HDIM + bx + tx];
    __syncthreads();
    for (int i = threadIdx.y; i < 32; i += 8) {
        float v = t[tx][i];                              // = W[by+tx][bx+i]
        size_t di = (size_t)(bx + i) * HDIM + by + tx;   // Wt[h][d]
        bf16 h = __float2bfloat16_rn(v);
        dh[di] = h;
        dl[di] = __float2bfloat16_rn(v - __bfloat162float(h));
    }
}

// ============================================================
// Kernel 4: pass A — mma.sync dual GEMM (h1, h3) + activation
//   Tile 128x64, 256 threads, 8 warps 4m x 2n (warp tile 32x32),
//   3-stage cp.async, 2 CTAs/SM. grid (16, 512, 3)
// ============================================================
#define A_STG  32768
#define A_NST  3
#define A_SMEM (2048 + A_NST * A_STG)

__global__ __launch_bounds__(256, 2)
void passA_mma(const float* __restrict__ b1, const float* __restrict__ b3) {
    int e    = blockIdx.z;
    int cnt  = g_cursor[e];
    int base = blockIdx.y * BM;
    if (base >= cnt) return;
    int n0  = blockIdx.x * BN;
    int tid = threadIdx.x, wid = tid >> 5, lane = tid & 31;
    int m32 = (wid & 3) * 32;        // 4 m-groups
    int n32 = (wid >> 2) * 32;       // 2 n-groups

    extern __shared__ char smem[];
    uint32_t sb = s2u(smem);

    int off = 0;
    for (int i = 0; i < e; i++) off += g_cursor[i];

    int*   srow = (int*)(smem);
    float* sb1  = (float*)(smem + 512);
    float* sb3  = (float*)(smem + 768);
    if (tid < BM) {
        int p = base + tid;
        srow[tid] = (p < cnt) ? g_idx[e * N_TOK + p] : g_idx[e * N_TOK];
    }
    if (tid < BN) {
        sb1[tid] = b1[e * HDIM + n0 + tid];
        sb3[tid] = b3[e * HDIM + n0 + tid];
    }
    __syncthreads();

    const bf16* w1h = g_w1hi + (size_t)e * HDIM * HDIM;
    const bf16* w1l = g_w1lo + (size_t)e * HDIM * HDIM;
    const bf16* w3h = g_w3hi + (size_t)e * HDIM * HDIM;
    const bf16* w3l = g_w3lo + (size_t)e * HDIM * HDIM;

    // ---- hoisted gather addressing (swizzle base + invariant offsets) ----
    int rr   = tid >> 3;                  // 0..31
    int cseg = (tid & 7) * 8;             // col within chunk
    uint32_t asw = swz((uint32_t)((rr << 7) | ((tid & 7) << 4)));
    size_t aoff[4];
    #pragma unroll
    for (int it = 0; it < 4; it++)
        aoff[it] = (size_t)srow[rr + 32 * it] * HDIM;
    size_t boff = (size_t)(n0 + rr) * HDIM;

    auto load_chunk = [&](int c) {
        int st  = c % A_NST;
        int kk0 = (c & 15) << 6;
        const bf16* As  = (c >= 16 && c < 32) ? g_xlo : g_xhi;
        const bf16* B1s = (c < 32) ? w1h : w1l;
        const bf16* B3s = (c < 32) ? w3h : w3l;
        uint32_t sa = sb + 2048 + st * A_STG;
        #pragma unroll
        for (int it = 0; it < 4; it++)
            cp16(sa + asw + it * 4096, As + aoff[it] + kk0 + cseg);
        #pragma unroll
        for (int it = 0; it < 2; it++) {
            size_t g = boff + (size_t)(it * 32) * HDIM + kk0 + cseg;
            cp16(sa + 16384 + asw + it * 4096, B1s + g);
            cp16(sa + 24576 + asw + it * 4096, B3s + g);
        }
        CP_COMMIT();
    };

    // ---- hoisted ldmatrix addressing ----
    int arow_lm = (lane & 15);
    int ahalf   = (lane >> 4);
    int nrow_lm = ((lane >> 4) << 3) + (lane & 7);
    int bhalf   = (lane >> 3) & 1;

    float acc1[2][4][4];
    float acc3[2][4][4];
    #pragma unroll
    for (int i = 0; i < 2; i++)
        #pragma unroll
        for (int j = 0; j < 4; j++)
            #pragma unroll
            for (int q = 0; q < 4; q++) { acc1[i][j][q] = 0.f; acc3[i][j][q] = 0.f; }

    load_chunk(0); load_chunk(1);

    for (int c = 0; c < NCH; c++) {
        CP_WAIT(1);
        __syncthreads();
        if (c + 2 < NCH) load_chunk(c + 2);
        else CP_COMMIT();                 // keep group count invariant for CP_WAIT(1)
        uint32_t sa = sb + 2048 + (c % A_NST) * A_STG;
        #pragma unroll
        for (int kk = 0; kk < 4; kk++) {
            uint32_t a[2][4];
            #pragma unroll
            for (int i = 0; i < 2; i++) {
                int row = m32 + i * 16 + arow_lm;
                uint32_t o = (uint32_t)(row * 128 + (kk * 2 + ahalf) * 16);
                LDSM4(a[i][0], a[i][1], a[i][2], a[i][3], sa + swz(o));
            }
            #pragma unroll
            for (int jj = 0; jj < 2; jj++) {
                int nrow = n32 + jj * 16 + nrow_lm;
                uint32_t sw = swz((uint32_t)(nrow * 128 + (kk * 2 + bhalf) * 16));
                uint32_t b0, b1r, b2r, b3r, c0, c1r, c2r, c3r;
                LDSM4(b0, b1r, b2r, b3r, sa + 16384 + sw);
                LDSM4(c0, c1r, c2r, c3r, sa + 24576 + sw);
                #pragma unroll
                for (int i = 0; i < 2; i++) {
                    MMA16816(acc1[i][2*jj],   a[i][0], a[i][1], a[i][2], a[i][3], b0, b1r);
                    MMA16816(acc1[i][2*jj+1], a[i][0], a[i][1], a[i][2], a[i][3], b2r, b3r);
                    MMA16816(acc3[i][2*jj],   a[i][0], a[i][1], a[i][2], a[i][3], c0, c1r);
                    MMA16816(acc3[i][2*jj+1], a[i][0], a[i][1], a[i][2], a[i][3], c2r, c3r);
                }
            }
        }
    }

    // epilogue: bias + activation, split-bf16 store of inner
    int mrows = cnt - base; if (mrows > BM) mrows = BM;
    #pragma unroll
    for (int i = 0; i < 2; i++) {
        int r0 = m32 + i * 16 + (lane >> 2);
        int r1 = r0 + 8;
        size_t g0 = (size_t)(off + base + r0) * HDIM;
        size_t g1 = (size_t)(off + base + r1) * HDIM;
        #pragma unroll
        for (int j = 0; j < 4; j++) {
            int n = n32 + j * 8 + (lane & 3) * 2;
            float bb1a = sb1[n], bb1b = sb1[n + 1];
            float bb3a = sb3[n], bb3b = sb3[n + 1];
            if (r0 < mrows) {
                float v0 = act_fn(acc1[i][j][0] + bb1a, e) * (acc3[i][j][0] + bb3a);
                float v1 = act_fn(acc1[i][j][1] + bb1b, e) * (acc3[i][j][1] + bb3b);
                bf16 h0 = __float2bfloat16_rn(v0), h1 = __float2bfloat16_rn(v1);
                *(uint32_t*)(g_ihi + g0 + n0 + n) = pack_bf2(v0, v1);
                *(uint32_t*)(g_ilo + g0 + n0 + n) =
                    pack_bf2(v0 - __bfloat162float(h0), v1 - __bfloat162float(h1));
            }
            if (r1 < mrows) {
                float v2 = act_fn(acc1[i][j][2] + bb1a, e) * (acc3[i][j][2] + bb3a);
                float v3 = act_fn(acc1[i][j][3] + bb1b, e) * (acc3[i][j][3] + bb3b);
                bf16 h2 = __float2bfloat16_rn(v2), h3 = __float2bfloat16_rn(v3);
                *(uint32_t*)(g_ihi + g1 + n0 + n) = pack_bf2(v2, v3);
                *(uint32_t*)(g_ilo + g1 + n0 + n) =
                    pack_bf2(v2 - __bfloat162float(h2), v3 - __bfloat162float(h3));
            }
        }
    }
}

// ============================================================
// Kernel 5: pass B — mma.sync GEMM inner@W2 + b2, scatter
//   Tile 128x64, 256 threads, 4m x 2n, 3-stage. grid (16, 512, 3)
// ============================================================
#define B_STG  24576
#define B_NST  3
#define B_SMEM (2048 + B_NST * B_STG)

__global__ __launch_bounds__(256, 2)
void passB_mma(const float* __restrict__ b2, float* __restrict__ out) {
    int e    = blockIdx.z;
    int cnt  = g_cursor[e];
    int base = blockIdx.y * BM;
    if (base >= cnt) return;
    int n0  = blockIdx.x * BN;
    int tid = threadIdx.x, wid = tid >> 5, lane = tid & 31;
    int m32 = (wid & 3) * 32;
    int n32 = (wid >> 2) * 32;

    extern __shared__ char smem[];
    uint32_t sb = s2u(smem);

    int off = 0;
    for (int i = 0; i < e; i++) off += g_cursor[i];

    int*   stok = (int*)(smem);
    float* sb2  = (float*)(smem + 512);
    if (tid < BM) {
        int p = base + tid;
        stok[tid] = (p < cnt) ? g_idx[e * N_TOK + p] : 0;
    }
    if (tid < BN) sb2[tid] = b2[e * HDIM + n0 + tid];
    __syncthreads();

    const bf16* w2h = g_w2hi + (size_t)e * HDIM * HDIM;
    const bf16* w2l = g_w2lo + (size_t)e * HDIM * HDIM;

    int rr   = tid >> 3;
    int cseg = (tid & 7) * 8;
    uint32_t asw = swz((uint32_t)((rr << 7) | ((tid & 7) << 4)));
    size_t aoff[4];
    #pragma unroll
    for (int it = 0; it < 4; it++) {
        int row  = rr + 32 * it;
        int arow = (base + row < cnt) ? (off + base + row) : off;
        aoff[it] = (size_t)arow * HDIM;
    }
    size_t boff = (size_t)(n0 + rr) * HDIM;

    auto load_chunk = [&](int c) {
        int st  = c % B_NST;
        int kk0 = (c & 15) << 6;
        const bf16* As = (c >= 16 && c < 32) ? g_ilo : g_ihi;
        const bf16* Bs = (c < 32) ? w2h : w2l;
        uint32_t sa = sb + 2048 + st * B_STG;
        #pragma unroll
        for (int it = 0; it < 4; it++)
            cp16(sa + asw + it * 4096, As + aoff[it] + kk0 + cseg);
        #pragma unroll
        for (int it = 0; it < 2; it++)
            cp16(sa + 16384 + asw + it * 4096,
                 Bs + boff + (size_t)(it * 32) * HDIM + kk0 + cseg);
        CP_COMMIT();
    };

    int arow_lm = (lane & 15);
    int ahalf   = (lane >> 4);
    int nrow_lm = ((lane >> 4) << 3) + (lane & 7);
    int bhalf   = (lane >> 3) & 1;

    float acc[2][4][4];
    #pragma unroll
    for (int i = 0; i < 2; i++)
        #pragma unroll
        for (int j = 0; j < 4; j++)
            #pragma unroll
            for (int q = 0; q < 4; q++) acc[i][j][q] = 0.f;

    load_chunk(0); load_chunk(1);

    for (int c = 0; c < NCH; c++) {
        CP_WAIT(1);
        __syncthreads();
        if (c + 2 < NCH) load_chunk(c + 2);
        else CP_COMMIT();
        uint32_t sa = sb + 2048 + (c % B_NST) * B_STG;
        #pragma unroll
        for (int kk = 0; kk < 4; kk++) {
            uint32_t a[2][4];
            #pragma unroll
            for (int i = 0; i < 2; i++) {
                int row = m32 + i * 16 + arow_lm;
                uint32_t o = (uint32_t)(row * 128 + (kk * 2 + ahalf) * 16);
                LDSM4(a[i][0], a[i][1], a[i][2], a[i][3], sa + swz(o));
            }
            #pragma unroll
            for (int jj = 0; jj < 2; jj++) {
                int nrow = n32 + jj * 16 + nrow_lm;
                uint32_t sw = swz((uint32_t)(nrow * 128 + (kk * 2 + bhalf) * 16));
                uint32_t b0, b1r, b2r, b3r;
                LDSM4(b0, b1r, b2r, b3r, sa + 16384 + sw);
                #pragma unroll
                for (int i = 0; i < 2; i++) {
                    MMA16816(acc[i][2*jj],   a[i][0], a[i][1], a[i][2], a[i][3], b0, b1r);
                    MMA16816(acc[i][2*jj+1], a[i][0], a[i][1], a[i][2], a[i][3], b2r, b3r);
                }
            }
        }
    }

    int mrows = cnt - base; if (mrows > BM) mrows = BM;
    #pragma unroll
    for (int i = 0; i < 2; i++) {
        int r0 = m32 + i * 16 + (lane >> 2);
        int r1 = r0 + 8;
        float* d0 = out + (size_t)stok[r0] * HDIM + n0;
        float* d1 = out + (size_t)stok[r1 < BM ? r1 : 0] * HDIM + n0;
        #pragma unroll
        for (int j = 0; j < 4; j++) {
            int n = n32 + j * 8 + (lane & 3) * 2;
            float ba = sb2[n], bb = sb2[n + 1];
            if (r0 < mrows) {
                float2 o0 = make_float2(acc[i][j][0] + ba, acc[i][j][1] + bb);
                *(float2*)(d0 + n) = o0;
            }
            if (r1 < mrows) {
                float2 o1 = make_float2(acc[i][j][2] + ba, acc[i][j][3] + bb);
                *(float2*)(d1 + n) = o1;
            }
        }
    }
}

// ============================================================
extern "C" void kernel_launch(void* const* d_in, const int* in_sizes, int n_in,
                              void* d_out, int out_size) {
    (void)in_sizes; (void)n_in; (void)out_size;
    const float* x  = (const float*)d_in[0];
    const float* W1 = (const float*)d_in[1];
    const float* b1 = (const float*)d_in[2];
    const float* W2 = (const float*)d_in[3];
    const float* b2 = (const float*)d_in[4];
    const float* W3 = (const float*)d_in[5];
    const float* b3 = (const float*)d_in[6];
    const float* Wg = (const float*)d_in[7];
    const float* bg = (const float*)d_in[8];
    const float* gu = (const float*)d_in[9];
    float* out = (float*)d_out;

    cudaFuncSetAttribute(passA_mma, cudaFuncAttributeMaxDynamicSharedMemorySize, A_SMEM);
    cudaFuncSetAttribute(passB_mma, cudaFuncAttributeMaxDynamicSharedMemorySize, B_SMEM);

    zero_kernel<<<1, 32>>>();
    gate_kernel<<<N_TOK / 8, 256>>>(x, Wg, bg, gu);
    xsplit_kernel<<<(int)(((size_t)N_TOK * HDIM) / 1024), 256>>>(x);
    {
        dim3 g(32, 32, 9), b(32, 8);
        wsplit_kernel<<<g, b>>>(W1, W3, W2);
    }
    {
        dim3 grid(HDIM / BN, N_TOK / BM, NEXP);
        passA_mma<<<grid, 256, A_SMEM>>>(b1, b3);
        passB_mma<<<grid, 256, B_SMEM>>>(b2, out);
    }
}